// round 12
// baseline (speedup 1.0000x reference)
#include <cuda_runtime.h>
#include <cuda_fp16.h>

// ---------------------------------------------------------------------------
// SSIM 3D, 11-tap separable Gaussian, VALID. Round 12:
// R7 pass bodies (measured best: 184.4us) with launch-count reduction:
//   - const_kernel folded into pass3 (C1/C2 from min/max bits inline)
//   - final_kernel folded into pass3 (last-block-done, fixed-order reduce)
// 4 launches instead of 6.
// ---------------------------------------------------------------------------

__device__ constexpr float CG[11] = {
    0.0010283817f, 0.0075987700f, 0.0360007700f, 0.1093607000f,
    0.2130055500f, 0.2660117200f,
    0.2130055500f, 0.1093607000f, 0.0360007700f, 0.0075987700f,
    0.0010283817f
};

// s1: [f][n][d][h(192)][w(184 pad, 182 valid)]   half
// s2: [f][n][d][oh(182)][w(184 pad, 182 valid)]  half
static const size_t FS1 = (size_t)2 * 192 * 192 * 184;   // 13,565,952 halves
static const size_t FS2 = (size_t)2 * 192 * 182 * 184;   // 12,859,392 halves
__device__ __half d_s1[5 * FS1];
__device__ __half d_s2[5 * FS2];

__device__ unsigned d_minbits;
__device__ unsigned d_maxbits;
__device__ unsigned d_count;
__device__ float    d_bsum[3623];

// ---------------------------------------------------------------------------

__global__ void init_kernel() {
    d_minbits = 0xFFFFFFFFu;
    d_maxbits = 0u;
    d_count   = 0u;
}

__device__ __forceinline__ float mono2f(unsigned u) {
    return (u & 0x80000000u) ? __uint_as_float(u ^ 0x80000000u)
                             : __uint_as_float(~u);
}
__device__ __forceinline__ void mono_acc(float f, unsigned& mn, unsigned& mx) {
    unsigned u = __float_as_uint(f);
    u = (u & 0x80000000u) ? ~u : (u | 0x80000000u);
    mn = min(mn, u);
    mx = max(mx, u);
}

// ---------------------------------------------------------------------------
// Pass 1: W conv + 5 products + img1 min/max. Block = (n,d, 8 h-rows).
// 192 threads; float4 smem fill; half2 stores. (Byte-identical to R7.)
// ---------------------------------------------------------------------------
__global__ void __launch_bounds__(192) pass1_kernel(
    const float* __restrict__ img1, const float* __restrict__ img2) {
    __shared__ float sx[8 * 192];
    __shared__ float sy[8 * 192];

    int hg = blockIdx.x % 24;
    int nd = blockIdx.x / 24;          // n*192 + d
    int h0 = hg * 8;
    size_t base = ((size_t)nd * 192 + h0) * 192;
    int tid = threadIdx.x;

    unsigned lmin = 0xFFFFFFFFu, lmax = 0u;
    const float4* p1 = (const float4*)(img1 + base);
    const float4* p2 = (const float4*)(img2 + base);
    #pragma unroll
    for (int j = 0; j < 2; j++) {
        int idx = tid + j * 192;       // 0..383 float4
        float4 a = __ldg(&p1[idx]);
        float4 b = __ldg(&p2[idx]);
        ((float4*)sx)[idx] = a;
        ((float4*)sy)[idx] = b;
        mono_acc(a.x, lmin, lmax); mono_acc(a.y, lmin, lmax);
        mono_acc(a.z, lmin, lmax); mono_acc(a.w, lmin, lmax);
    }
    __syncthreads();

    size_t ob = ((size_t)nd * 192 + h0) * 184;
    for (int i = tid; i < 8 * 91; i += 192) {
        int r = i / 91;
        int p = (i % 91) * 2;          // ow pair: p, p+1
        float a0l = 0.f, a1l = 0.f, a2l = 0.f, a3l = 0.f, a4l = 0.f;
        float a0h = 0.f, a1h = 0.f, a2h = 0.f, a3h = 0.f, a4h = 0.f;
        #pragma unroll
        for (int k = 0; k < 11; k++) {
            float g = CG[k];
            float x = sx[r * 192 + p + k];
            float y = sy[r * 192 + p + k];
            float tx = g * x, ty = g * y;
            a0l += tx; a1l += ty; a2l += tx * x; a3l += ty * y; a4l += tx * y;
            float x2 = sx[r * 192 + p + 1 + k];
            float y2 = sy[r * 192 + p + 1 + k];
            float tx2 = g * x2, ty2 = g * y2;
            a0h += tx2; a1h += ty2; a2h += tx2 * x2; a3h += ty2 * y2; a4h += tx2 * y2;
        }
        size_t o = ob + (size_t)r * 184 + p;
        *(__half2*)&d_s1[o]           = __floats2half2_rn(a0l, a0h);
        *(__half2*)&d_s1[FS1 + o]     = __floats2half2_rn(a1l, a1h);
        *(__half2*)&d_s1[2 * FS1 + o] = __floats2half2_rn(a2l, a2h);
        *(__half2*)&d_s1[3 * FS1 + o] = __floats2half2_rn(a3l, a3h);
        *(__half2*)&d_s1[4 * FS1 + o] = __floats2half2_rn(a4l, a4h);
    }

    // min/max block reduce -> atomics
    #pragma unroll
    for (int off = 16; off; off >>= 1) {
        lmin = min(lmin, __shfl_down_sync(0xFFFFFFFFu, lmin, off));
        lmax = max(lmax, __shfl_down_sync(0xFFFFFFFFu, lmax, off));
    }
    __shared__ unsigned smin[6], smax[6];
    int wid = tid >> 5, lane = tid & 31;
    if (lane == 0) { smin[wid] = lmin; smax[wid] = lmax; }
    __syncthreads();
    if (tid == 0) {
        #pragma unroll
        for (int i = 1; i < 6; i++) {
            lmin = min(lmin, smin[i]);
            lmax = max(lmax, smax[i]);
        }
        atomicMin(&d_minbits, lmin);
        atomicMax(&d_maxbits, lmax);
    }
}

// ---------------------------------------------------------------------------
// Pass 2: H conv, half2 loads, fp32 accumulation (52 accums), strips of 26.
// Thread = (nd desc, f, strip, owp). (Byte-identical to R7.)
// ---------------------------------------------------------------------------
__global__ void __launch_bounds__(256) pass2_kernel() {
    const size_t TOT = (size_t)5 * 2 * 192 * 7 * 91;     // 1,223,040
    size_t idx = (size_t)blockIdx.x * 256 + threadIdx.x;
    if (idx >= TOT) return;
    int owp = (int)(idx % 91); size_t t = idx / 91;
    int strip = (int)(t % 7); t /= 7;
    int f   = (int)(t % 5);
    int nd  = 383 - (int)(t / 5);        // descending: hit pass1's L2 tail
    int h0 = strip * 26;
    int ow = owp * 2;

    const __half* __restrict__ src = d_s1 + (size_t)f * FS1 + (size_t)nd * (192 * 184) + ow;
    __half* __restrict__ dst = d_s2 + (size_t)f * FS2 + (size_t)nd * (182 * 184) + ow;

    float accl[26], acch[26];
    #pragma unroll
    for (int o = 0; o < 26; o++) { accl[o] = 0.f; acch[o] = 0.f; }

    #pragma unroll
    for (int j = 0; j < 36; j++) {
        __half2 h = __ldg((const __half2*)&src[(size_t)(h0 + j) * 184]);
        float vl = __low2float(h), vh = __high2float(h);
        #pragma unroll
        for (int o = 0; o < 26; o++) {
            int k = j - o;
            if (k >= 0 && k < 11) {
                accl[o] += CG[k] * vl;
                acch[o] += CG[k] * vh;
            }
        }
    }
    #pragma unroll
    for (int o = 0; o < 26; o++)
        *(__half2*)&dst[(size_t)(h0 + o) * 184] = __floats2half2_rn(accl[o], acch[o]);
}

// ---------------------------------------------------------------------------
// Pass 3: D conv (5 fields) + SSIM + block sum + last-block final reduce.
// Thread = (n, strip, oh, ow). Strips of 13, 65 fp32 accumulators.
// ---------------------------------------------------------------------------
__global__ void __launch_bounds__(256) pass3_kernel(float* __restrict__ out) {
    const size_t TOT = (size_t)2 * 14 * 182 * 182;   // 927,472
    size_t idx = (size_t)blockIdx.x * 256 + threadIdx.x;
    float lsum = 0.f;
    if (idx < TOT) {
        int ow = (int)(idx % 182); size_t t = idx / 182;
        int oh = (int)(t % 182); t /= 182;
        int strip = (int)(t % 14);
        int n = (int)(t / 14);
        int d0 = strip * 13;

        float mx = mono2f(d_maxbits);
        float mn = mono2f(d_minbits);
        float max_val = (mx > 128.0f) ? 255.0f : 1.0f;
        float min_val = (mn < -0.5f) ? -1.0f : 0.0f;
        float L = max_val - min_val;
        float c1 = 0.01f * L, c2 = 0.03f * L;
        const float C1 = c1 * c1;
        const float C2 = c2 * c2;

        float a0[13], a1[13], a2[13], a3[13], a4[13];
        #pragma unroll
        for (int o = 0; o < 13; o++) {
            a0[o] = 0.f; a1[o] = 0.f; a2[o] = 0.f; a3[o] = 0.f; a4[o] = 0.f;
        }
        // s2 offset: ((n*192 + d)*182 + oh)*184 + ow ; d-stride = 182*184 = 33488
        size_t pbase = ((size_t)(n * 192 + d0) * 182 + oh) * 184 + ow;
        #pragma unroll
        for (int j = 0; j < 23; j++) {
            size_t p = pbase + (size_t)j * 33488;
            float m1  = __half2float(__ldg(&d_s2[p]));
            float m2  = __half2float(__ldg(&d_s2[p + FS2]));
            float e11 = __half2float(__ldg(&d_s2[p + 2 * FS2]));
            float e22 = __half2float(__ldg(&d_s2[p + 3 * FS2]));
            float e12 = __half2float(__ldg(&d_s2[p + 4 * FS2]));
            #pragma unroll
            for (int o = 0; o < 13; o++) {
                int k = j - o;
                if (k >= 0 && k < 11) {
                    float g = CG[k];
                    a0[o] += g * m1;
                    a1[o] += g * m2;
                    a2[o] += g * e11;
                    a3[o] += g * e22;
                    a4[o] += g * e12;
                }
            }
        }
        #pragma unroll
        for (int o = 0; o < 13; o++) {
            float mu1 = a0[o], mu2 = a1[o];
            float m11 = mu1 * mu1, m22 = mu2 * mu2, m12 = mu1 * mu2;
            float s11 = a2[o] - m11;
            float s22 = a3[o] - m22;
            float s12 = a4[o] - m12;
            float v1 = 2.f * s12 + C2;
            float v2 = s11 + s22 + C2;
            float num = (2.f * m12 + C1) * v1;
            float den = (m11 + m22 + C1) * v2;
            lsum += __fdividef(num, den);
        }
    }
    __shared__ float sred[256];
    sred[threadIdx.x] = lsum;
    __syncthreads();
    #pragma unroll
    for (int off = 128; off; off >>= 1) {
        if (threadIdx.x < off) sred[threadIdx.x] += sred[threadIdx.x + off];
        __syncthreads();
    }

    // last-block-done final reduction (deterministic fixed-order sum)
    __shared__ int s_last;
    if (threadIdx.x == 0) {
        d_bsum[blockIdx.x] = sred[0];
        __threadfence();
        unsigned ticket = atomicInc(&d_count, gridDim.x - 1);  // wraps to 0
        s_last = (ticket == gridDim.x - 1);
    }
    __syncthreads();
    if (s_last) {
        __threadfence();
        __shared__ double sd[256];
        double s = 0.0;
        for (int i = threadIdx.x; i < 3623; i += 256) s += (double)d_bsum[i];
        sd[threadIdx.x] = s;
        __syncthreads();
        #pragma unroll
        for (int off = 128; off; off >>= 1) {
            if (threadIdx.x < off) sd[threadIdx.x] += sd[threadIdx.x + off];
            __syncthreads();
        }
        if (threadIdx.x == 0)
            out[0] = (float)(sd[0] / 12057136.0);   // 2 * 182^3
    }
}

// ---------------------------------------------------------------------------

extern "C" void kernel_launch(void* const* d_in, const int* in_sizes, int n_in,
                              void* d_out, int out_size) {
    const float* img1 = (const float*)d_in[0];
    const float* img2 = (const float*)d_in[1];
    float* out = (float*)d_out;

    init_kernel<<<1, 1>>>();
    pass1_kernel<<<9216, 192>>>(img1, img2);   // 2*192*192 rows / 8
    pass2_kernel<<<4778, 256>>>();             // 5*2*192*7*91 threads
    pass3_kernel<<<3623, 256>>>(out);          // 2*14*182*182 threads + final
}

// round 13
// speedup vs baseline: 1.0662x; 1.0662x over previous
#include <cuda_runtime.h>
#include <cuda_fp16.h>

// ---------------------------------------------------------------------------
// SSIM 3D, 11-tap separable Gaussian, VALID. Round 13:
// Exact R7 (best: 184.4us) except pass3: 2-ow/thread with fma.rn.f32x2
// accumulators (both lanes always valid; identical fp32 rounding/order).
// ---------------------------------------------------------------------------

typedef unsigned long long ull;

__device__ constexpr float CG[11] = {
    0.0010283817f, 0.0075987700f, 0.0360007700f, 0.1093607000f,
    0.2130055500f, 0.2660117200f,
    0.2130055500f, 0.1093607000f, 0.0360007700f, 0.0075987700f,
    0.0010283817f
};

__device__ __forceinline__ ull f2pack(float lo, float hi) {
    ull r; asm("mov.b64 %0, {%1, %2};" : "=l"(r) : "f"(lo), "f"(hi)); return r;
}
__device__ __forceinline__ float2 f2unpack(ull v) {
    float2 r; asm("mov.b64 {%0, %1}, %2;" : "=f"(r.x), "=f"(r.y) : "l"(v)); return r;
}
__device__ __forceinline__ ull f2fma(ull a, ull b, ull c) {
    ull d; asm("fma.rn.f32x2 %0, %1, %2, %3;" : "=l"(d) : "l"(a), "l"(b), "l"(c)); return d;
}

// s1: [f][n][d][h(192)][w(184 pad, 182 valid)]   half
// s2: [f][n][d][oh(182)][w(184 pad, 182 valid)]  half
static const size_t FS1 = (size_t)2 * 192 * 192 * 184;   // 13,565,952 halves
static const size_t FS2 = (size_t)2 * 192 * 182 * 184;   // 12,859,392 halves
__device__ __half d_s1[5 * FS1];
__device__ __half d_s2[5 * FS2];

__device__ unsigned d_minbits;
__device__ unsigned d_maxbits;
__device__ float    d_c1c2[2];
__device__ float    d_bsum[1812];

// ---------------------------------------------------------------------------

__global__ void init_kernel() {
    d_minbits = 0xFFFFFFFFu;
    d_maxbits = 0u;
}

__device__ __forceinline__ float mono2f(unsigned u) {
    return (u & 0x80000000u) ? __uint_as_float(u ^ 0x80000000u)
                             : __uint_as_float(~u);
}
__device__ __forceinline__ void mono_acc(float f, unsigned& mn, unsigned& mx) {
    unsigned u = __float_as_uint(f);
    u = (u & 0x80000000u) ? ~u : (u | 0x80000000u);
    mn = min(mn, u);
    mx = max(mx, u);
}

__global__ void const_kernel() {
    float mx = mono2f(d_maxbits);
    float mn = mono2f(d_minbits);
    float max_val = (mx > 128.0f) ? 255.0f : 1.0f;
    float min_val = (mn < -0.5f) ? -1.0f : 0.0f;
    float L = max_val - min_val;
    float c1 = 0.01f * L, c2 = 0.03f * L;
    d_c1c2[0] = c1 * c1;
    d_c1c2[1] = c2 * c2;
}

// ---------------------------------------------------------------------------
// Pass 1: W conv + 5 products + img1 min/max. Block = (n,d, 8 h-rows).
// 192 threads; float4 smem fill; half2 stores. (Byte-identical to R7.)
// ---------------------------------------------------------------------------
__global__ void __launch_bounds__(192) pass1_kernel(
    const float* __restrict__ img1, const float* __restrict__ img2) {
    __shared__ float sx[8 * 192];
    __shared__ float sy[8 * 192];

    int hg = blockIdx.x % 24;
    int nd = blockIdx.x / 24;          // n*192 + d
    int h0 = hg * 8;
    size_t base = ((size_t)nd * 192 + h0) * 192;
    int tid = threadIdx.x;

    unsigned lmin = 0xFFFFFFFFu, lmax = 0u;
    const float4* p1 = (const float4*)(img1 + base);
    const float4* p2 = (const float4*)(img2 + base);
    #pragma unroll
    for (int j = 0; j < 2; j++) {
        int idx = tid + j * 192;       // 0..383 float4
        float4 a = __ldg(&p1[idx]);
        float4 b = __ldg(&p2[idx]);
        ((float4*)sx)[idx] = a;
        ((float4*)sy)[idx] = b;
        mono_acc(a.x, lmin, lmax); mono_acc(a.y, lmin, lmax);
        mono_acc(a.z, lmin, lmax); mono_acc(a.w, lmin, lmax);
    }
    __syncthreads();

    size_t ob = ((size_t)nd * 192 + h0) * 184;
    for (int i = tid; i < 8 * 91; i += 192) {
        int r = i / 91;
        int p = (i % 91) * 2;          // ow pair: p, p+1
        float a0l = 0.f, a1l = 0.f, a2l = 0.f, a3l = 0.f, a4l = 0.f;
        float a0h = 0.f, a1h = 0.f, a2h = 0.f, a3h = 0.f, a4h = 0.f;
        #pragma unroll
        for (int k = 0; k < 11; k++) {
            float g = CG[k];
            float x = sx[r * 192 + p + k];
            float y = sy[r * 192 + p + k];
            float tx = g * x, ty = g * y;
            a0l += tx; a1l += ty; a2l += tx * x; a3l += ty * y; a4l += tx * y;
            float x2 = sx[r * 192 + p + 1 + k];
            float y2 = sy[r * 192 + p + 1 + k];
            float tx2 = g * x2, ty2 = g * y2;
            a0h += tx2; a1h += ty2; a2h += tx2 * x2; a3h += ty2 * y2; a4h += tx2 * y2;
        }
        size_t o = ob + (size_t)r * 184 + p;
        *(__half2*)&d_s1[o]           = __floats2half2_rn(a0l, a0h);
        *(__half2*)&d_s1[FS1 + o]     = __floats2half2_rn(a1l, a1h);
        *(__half2*)&d_s1[2 * FS1 + o] = __floats2half2_rn(a2l, a2h);
        *(__half2*)&d_s1[3 * FS1 + o] = __floats2half2_rn(a3l, a3h);
        *(__half2*)&d_s1[4 * FS1 + o] = __floats2half2_rn(a4l, a4h);
    }

    // min/max block reduce -> atomics
    #pragma unroll
    for (int off = 16; off; off >>= 1) {
        lmin = min(lmin, __shfl_down_sync(0xFFFFFFFFu, lmin, off));
        lmax = max(lmax, __shfl_down_sync(0xFFFFFFFFu, lmax, off));
    }
    __shared__ unsigned smin[6], smax[6];
    int wid = tid >> 5, lane = tid & 31;
    if (lane == 0) { smin[wid] = lmin; smax[wid] = lmax; }
    __syncthreads();
    if (tid == 0) {
        #pragma unroll
        for (int i = 1; i < 6; i++) {
            lmin = min(lmin, smin[i]);
            lmax = max(lmax, smax[i]);
        }
        atomicMin(&d_minbits, lmin);
        atomicMax(&d_maxbits, lmax);
    }
}

// ---------------------------------------------------------------------------
// Pass 2: H conv, half2 loads, fp32 accumulation (52 accums), strips of 26.
// Thread = (nd desc, f, strip, owp). (Byte-identical to R7.)
// ---------------------------------------------------------------------------
__global__ void __launch_bounds__(256) pass2_kernel() {
    const size_t TOT = (size_t)5 * 2 * 192 * 7 * 91;     // 1,223,040
    size_t idx = (size_t)blockIdx.x * 256 + threadIdx.x;
    if (idx >= TOT) return;
    int owp = (int)(idx % 91); size_t t = idx / 91;
    int strip = (int)(t % 7); t /= 7;
    int f   = (int)(t % 5);
    int nd  = 383 - (int)(t / 5);        // descending: hit pass1's L2 tail
    int h0 = strip * 26;
    int ow = owp * 2;

    const __half* __restrict__ src = d_s1 + (size_t)f * FS1 + (size_t)nd * (192 * 184) + ow;
    __half* __restrict__ dst = d_s2 + (size_t)f * FS2 + (size_t)nd * (182 * 184) + ow;

    float accl[26], acch[26];
    #pragma unroll
    for (int o = 0; o < 26; o++) { accl[o] = 0.f; acch[o] = 0.f; }

    #pragma unroll
    for (int j = 0; j < 36; j++) {
        __half2 h = __ldg((const __half2*)&src[(size_t)(h0 + j) * 184]);
        float vl = __low2float(h), vh = __high2float(h);
        #pragma unroll
        for (int o = 0; o < 26; o++) {
            int k = j - o;
            if (k >= 0 && k < 11) {
                accl[o] += CG[k] * vl;
                acch[o] += CG[k] * vh;
            }
        }
    }
    #pragma unroll
    for (int o = 0; o < 26; o++)
        *(__half2*)&dst[(size_t)(h0 + o) * 184] = __floats2half2_rn(accl[o], acch[o]);
}

// ---------------------------------------------------------------------------
// Pass 3: D conv (5 fields) + SSIM + block sum. Thread = (n, strip, oh, owp)
// with 2 adjacent ow per thread. Strips of 13. f32x2 accumulators: both
// lanes always valid, coefficient = packed broadcast constant. fp32 exact.
// ---------------------------------------------------------------------------
__global__ void __launch_bounds__(256) pass3_kernel() {
    const size_t TOT = (size_t)2 * 14 * 182 * 91;   // 463,736
    size_t idx = (size_t)blockIdx.x * 256 + threadIdx.x;
    float lsum = 0.f;
    if (idx < TOT) {
        int owp = (int)(idx % 91); size_t t = idx / 91;
        int oh = (int)(t % 182); t /= 182;
        int strip = (int)(t % 14);
        int n = (int)(t / 14);
        int d0 = strip * 13;
        const float C1 = d_c1c2[0];
        const float C2 = d_c1c2[1];

        ull a0[13], a1[13], a2[13], a3[13], a4[13];
        #pragma unroll
        for (int o = 0; o < 13; o++) {
            a0[o] = 0; a1[o] = 0; a2[o] = 0; a3[o] = 0; a4[o] = 0;
        }
        // s2 offset: ((n*192 + d)*182 + oh)*184 + ow ; d-stride = 182*184 = 33488
        size_t pbase = ((size_t)(n * 192 + d0) * 182 + oh) * 184 + (size_t)(owp * 2);
        #pragma unroll
        for (int j = 0; j < 23; j++) {
            size_t p = pbase + (size_t)j * 33488;
            float2 vm1 = __half22float2(__ldg((const __half2*)&d_s2[p]));
            float2 vm2 = __half22float2(__ldg((const __half2*)&d_s2[p + FS2]));
            float2 v11 = __half22float2(__ldg((const __half2*)&d_s2[p + 2 * FS2]));
            float2 v22 = __half22float2(__ldg((const __half2*)&d_s2[p + 3 * FS2]));
            float2 v12 = __half22float2(__ldg((const __half2*)&d_s2[p + 4 * FS2]));
            ull M1  = f2pack(vm1.x, vm1.y);
            ull M2  = f2pack(vm2.x, vm2.y);
            ull E11 = f2pack(v11.x, v11.y);
            ull E22 = f2pack(v22.x, v22.y);
            ull E12 = f2pack(v12.x, v12.y);
            #pragma unroll
            for (int o = 0; o < 13; o++) {
                int k = j - o;
                if (k >= 0 && k < 11) {
                    ull G = f2pack(CG[k], CG[k]);   // compile-time broadcast
                    a0[o] = f2fma(G, M1,  a0[o]);
                    a1[o] = f2fma(G, M2,  a1[o]);
                    a2[o] = f2fma(G, E11, a2[o]);
                    a3[o] = f2fma(G, E22, a3[o]);
                    a4[o] = f2fma(G, E12, a4[o]);
                }
            }
        }
        #pragma unroll
        for (int o = 0; o < 13; o++) {
            float2 MU1 = f2unpack(a0[o]);
            float2 MU2 = f2unpack(a1[o]);
            float2 E11 = f2unpack(a2[o]);
            float2 E22 = f2unpack(a3[o]);
            float2 E12 = f2unpack(a4[o]);
            #pragma unroll
            for (int l = 0; l < 2; l++) {
                float mu1 = l ? MU1.y : MU1.x;
                float mu2 = l ? MU2.y : MU2.x;
                float e11 = l ? E11.y : E11.x;
                float e22 = l ? E22.y : E22.x;
                float e12 = l ? E12.y : E12.x;
                float m11 = mu1 * mu1, m22 = mu2 * mu2, m12 = mu1 * mu2;
                float s11 = e11 - m11;
                float s22 = e22 - m22;
                float s12 = e12 - m12;
                float v1 = 2.f * s12 + C2;
                float v2 = s11 + s22 + C2;
                float num = (2.f * m12 + C1) * v1;
                float den = (m11 + m22 + C1) * v2;
                lsum += __fdividef(num, den);
            }
        }
    }
    __shared__ float sred[256];
    sred[threadIdx.x] = lsum;
    __syncthreads();
    #pragma unroll
    for (int off = 128; off; off >>= 1) {
        if (threadIdx.x < off) sred[threadIdx.x] += sred[threadIdx.x + off];
        __syncthreads();
    }
    if (threadIdx.x == 0) d_bsum[blockIdx.x] = sred[0];
}

// Deterministic final reduction over 1812 block sums.
__global__ void final_kernel(float* __restrict__ out) {
    __shared__ double sd[256];
    double s = 0.0;
    for (int i = threadIdx.x; i < 1812; i += 256) s += (double)d_bsum[i];
    sd[threadIdx.x] = s;
    __syncthreads();
    #pragma unroll
    for (int off = 128; off; off >>= 1) {
        if (threadIdx.x < off) sd[threadIdx.x] += sd[threadIdx.x + off];
        __syncthreads();
    }
    if (threadIdx.x == 0)
        out[0] = (float)(sd[0] / 12057136.0);   // 2 * 182^3
}

// ---------------------------------------------------------------------------

extern "C" void kernel_launch(void* const* d_in, const int* in_sizes, int n_in,
                              void* d_out, int out_size) {
    const float* img1 = (const float*)d_in[0];
    const float* img2 = (const float*)d_in[1];
    float* out = (float*)d_out;

    init_kernel<<<1, 1>>>();
    pass1_kernel<<<9216, 192>>>(img1, img2);   // 2*192*192 rows / 8
    const_kernel<<<1, 1>>>();
    pass2_kernel<<<4778, 256>>>();             // 5*2*192*7*91 threads
    pass3_kernel<<<1812, 256>>>();             // 2*14*182*91 threads (2 ow each)
    final_kernel<<<1, 256>>>(out);
}

// round 14
// speedup vs baseline: 1.0801x; 1.0130x over previous
#include <cuda_runtime.h>
#include <cuda_fp16.h>

// ---------------------------------------------------------------------------
// SSIM 3D, 11-tap separable Gaussian, VALID. Round 14:
// R13 (best: 178.9us) +
//   - pass3 block order (owp, strip, oh, n): strip varies fast so each
//     strip's 10-row halo is the L2-hot body of the adjacent strip
//   - const_kernel folded into pass3 (C1/C2 from min/max bits inline)
// ---------------------------------------------------------------------------

typedef unsigned long long ull;

__device__ constexpr float CG[11] = {
    0.0010283817f, 0.0075987700f, 0.0360007700f, 0.1093607000f,
    0.2130055500f, 0.2660117200f,
    0.2130055500f, 0.1093607000f, 0.0360007700f, 0.0075987700f,
    0.0010283817f
};

__device__ __forceinline__ ull f2pack(float lo, float hi) {
    ull r; asm("mov.b64 %0, {%1, %2};" : "=l"(r) : "f"(lo), "f"(hi)); return r;
}
__device__ __forceinline__ float2 f2unpack(ull v) {
    float2 r; asm("mov.b64 {%0, %1}, %2;" : "=f"(r.x), "=f"(r.y) : "l"(v)); return r;
}
__device__ __forceinline__ ull f2fma(ull a, ull b, ull c) {
    ull d; asm("fma.rn.f32x2 %0, %1, %2, %3;" : "=l"(d) : "l"(a), "l"(b), "l"(c)); return d;
}

// s1: [f][n][d][h(192)][w(184 pad, 182 valid)]   half
// s2: [f][n][d][oh(182)][w(184 pad, 182 valid)]  half
static const size_t FS1 = (size_t)2 * 192 * 192 * 184;   // 13,565,952 halves
static const size_t FS2 = (size_t)2 * 192 * 182 * 184;   // 12,859,392 halves
__device__ __half d_s1[5 * FS1];
__device__ __half d_s2[5 * FS2];

__device__ unsigned d_minbits;
__device__ unsigned d_maxbits;
__device__ float    d_bsum[1812];

// ---------------------------------------------------------------------------

__global__ void init_kernel() {
    d_minbits = 0xFFFFFFFFu;
    d_maxbits = 0u;
}

__device__ __forceinline__ float mono2f(unsigned u) {
    return (u & 0x80000000u) ? __uint_as_float(u ^ 0x80000000u)
                             : __uint_as_float(~u);
}
__device__ __forceinline__ void mono_acc(float f, unsigned& mn, unsigned& mx) {
    unsigned u = __float_as_uint(f);
    u = (u & 0x80000000u) ? ~u : (u | 0x80000000u);
    mn = min(mn, u);
    mx = max(mx, u);
}

// ---------------------------------------------------------------------------
// Pass 1: W conv + 5 products + img1 min/max. Block = (n,d, 8 h-rows).
// 192 threads; float4 smem fill; half2 stores. (Byte-identical to R7/R13.)
// ---------------------------------------------------------------------------
__global__ void __launch_bounds__(192) pass1_kernel(
    const float* __restrict__ img1, const float* __restrict__ img2) {
    __shared__ float sx[8 * 192];
    __shared__ float sy[8 * 192];

    int hg = blockIdx.x % 24;
    int nd = blockIdx.x / 24;          // n*192 + d
    int h0 = hg * 8;
    size_t base = ((size_t)nd * 192 + h0) * 192;
    int tid = threadIdx.x;

    unsigned lmin = 0xFFFFFFFFu, lmax = 0u;
    const float4* p1 = (const float4*)(img1 + base);
    const float4* p2 = (const float4*)(img2 + base);
    #pragma unroll
    for (int j = 0; j < 2; j++) {
        int idx = tid + j * 192;       // 0..383 float4
        float4 a = __ldg(&p1[idx]);
        float4 b = __ldg(&p2[idx]);
        ((float4*)sx)[idx] = a;
        ((float4*)sy)[idx] = b;
        mono_acc(a.x, lmin, lmax); mono_acc(a.y, lmin, lmax);
        mono_acc(a.z, lmin, lmax); mono_acc(a.w, lmin, lmax);
    }
    __syncthreads();

    size_t ob = ((size_t)nd * 192 + h0) * 184;
    for (int i = tid; i < 8 * 91; i += 192) {
        int r = i / 91;
        int p = (i % 91) * 2;          // ow pair: p, p+1
        float a0l = 0.f, a1l = 0.f, a2l = 0.f, a3l = 0.f, a4l = 0.f;
        float a0h = 0.f, a1h = 0.f, a2h = 0.f, a3h = 0.f, a4h = 0.f;
        #pragma unroll
        for (int k = 0; k < 11; k++) {
            float g = CG[k];
            float x = sx[r * 192 + p + k];
            float y = sy[r * 192 + p + k];
            float tx = g * x, ty = g * y;
            a0l += tx; a1l += ty; a2l += tx * x; a3l += ty * y; a4l += tx * y;
            float x2 = sx[r * 192 + p + 1 + k];
            float y2 = sy[r * 192 + p + 1 + k];
            float tx2 = g * x2, ty2 = g * y2;
            a0h += tx2; a1h += ty2; a2h += tx2 * x2; a3h += ty2 * y2; a4h += tx2 * y2;
        }
        size_t o = ob + (size_t)r * 184 + p;
        *(__half2*)&d_s1[o]           = __floats2half2_rn(a0l, a0h);
        *(__half2*)&d_s1[FS1 + o]     = __floats2half2_rn(a1l, a1h);
        *(__half2*)&d_s1[2 * FS1 + o] = __floats2half2_rn(a2l, a2h);
        *(__half2*)&d_s1[3 * FS1 + o] = __floats2half2_rn(a3l, a3h);
        *(__half2*)&d_s1[4 * FS1 + o] = __floats2half2_rn(a4l, a4h);
    }

    // min/max block reduce -> atomics
    #pragma unroll
    for (int off = 16; off; off >>= 1) {
        lmin = min(lmin, __shfl_down_sync(0xFFFFFFFFu, lmin, off));
        lmax = max(lmax, __shfl_down_sync(0xFFFFFFFFu, lmax, off));
    }
    __shared__ unsigned smin[6], smax[6];
    int wid = tid >> 5, lane = tid & 31;
    if (lane == 0) { smin[wid] = lmin; smax[wid] = lmax; }
    __syncthreads();
    if (tid == 0) {
        #pragma unroll
        for (int i = 1; i < 6; i++) {
            lmin = min(lmin, smin[i]);
            lmax = max(lmax, smax[i]);
        }
        atomicMin(&d_minbits, lmin);
        atomicMax(&d_maxbits, lmax);
    }
}

// ---------------------------------------------------------------------------
// Pass 2: H conv, half2 loads, fp32 accumulation (52 accums), strips of 26.
// Thread = (nd desc, f, strip, owp). (Byte-identical to R7/R13.)
// ---------------------------------------------------------------------------
__global__ void __launch_bounds__(256) pass2_kernel() {
    const size_t TOT = (size_t)5 * 2 * 192 * 7 * 91;     // 1,223,040
    size_t idx = (size_t)blockIdx.x * 256 + threadIdx.x;
    if (idx >= TOT) return;
    int owp = (int)(idx % 91); size_t t = idx / 91;
    int strip = (int)(t % 7); t /= 7;
    int f   = (int)(t % 5);
    int nd  = 383 - (int)(t / 5);        // descending: hit pass1's L2 tail
    int h0 = strip * 26;
    int ow = owp * 2;

    const __half* __restrict__ src = d_s1 + (size_t)f * FS1 + (size_t)nd * (192 * 184) + ow;
    __half* __restrict__ dst = d_s2 + (size_t)f * FS2 + (size_t)nd * (182 * 184) + ow;

    float accl[26], acch[26];
    #pragma unroll
    for (int o = 0; o < 26; o++) { accl[o] = 0.f; acch[o] = 0.f; }

    #pragma unroll
    for (int j = 0; j < 36; j++) {
        __half2 h = __ldg((const __half2*)&src[(size_t)(h0 + j) * 184]);
        float vl = __low2float(h), vh = __high2float(h);
        #pragma unroll
        for (int o = 0; o < 26; o++) {
            int k = j - o;
            if (k >= 0 && k < 11) {
                accl[o] += CG[k] * vl;
                acch[o] += CG[k] * vh;
            }
        }
    }
    #pragma unroll
    for (int o = 0; o < 26; o++)
        *(__half2*)&dst[(size_t)(h0 + o) * 184] = __floats2half2_rn(accl[o], acch[o]);
}

// ---------------------------------------------------------------------------
// Pass 3: D conv (5 fields) + SSIM + block sum. Thread = (n, oh, strip, owp),
// strip varies FAST so adjacent blocks share halo rows through L2.
// 2 adjacent ow per thread; f32x2 accumulators (fp32-exact).
// C1/C2 derived inline from min/max bits.
// ---------------------------------------------------------------------------
__global__ void __launch_bounds__(256) pass3_kernel() {
    const size_t TOT = (size_t)2 * 182 * 14 * 91;   // 463,736
    size_t idx = (size_t)blockIdx.x * 256 + threadIdx.x;
    float lsum = 0.f;
    if (idx < TOT) {
        int owp = (int)(idx % 91); size_t t = idx / 91;
        int strip = (int)(t % 14); t /= 14;          // strip fast: halo L2 reuse
        int oh = (int)(t % 182);
        int n  = (int)(t / 182);
        int d0 = strip * 13;

        float mxv = mono2f(d_maxbits);
        float mnv = mono2f(d_minbits);
        float max_val = (mxv > 128.0f) ? 255.0f : 1.0f;
        float min_val = (mnv < -0.5f) ? -1.0f : 0.0f;
        float Lr = max_val - min_val;
        float c1 = 0.01f * Lr, c2 = 0.03f * Lr;
        const float C1 = c1 * c1;
        const float C2 = c2 * c2;

        ull a0[13], a1[13], a2[13], a3[13], a4[13];
        #pragma unroll
        for (int o = 0; o < 13; o++) {
            a0[o] = 0; a1[o] = 0; a2[o] = 0; a3[o] = 0; a4[o] = 0;
        }
        // s2 offset: ((n*192 + d)*182 + oh)*184 + ow ; d-stride = 182*184 = 33488
        size_t pbase = ((size_t)(n * 192 + d0) * 182 + oh) * 184 + (size_t)(owp * 2);
        #pragma unroll
        for (int j = 0; j < 23; j++) {
            size_t p = pbase + (size_t)j * 33488;
            float2 vm1 = __half22float2(__ldg((const __half2*)&d_s2[p]));
            float2 vm2 = __half22float2(__ldg((const __half2*)&d_s2[p + FS2]));
            float2 v11 = __half22float2(__ldg((const __half2*)&d_s2[p + 2 * FS2]));
            float2 v22 = __half22float2(__ldg((const __half2*)&d_s2[p + 3 * FS2]));
            float2 v12 = __half22float2(__ldg((const __half2*)&d_s2[p + 4 * FS2]));
            ull M1  = f2pack(vm1.x, vm1.y);
            ull M2  = f2pack(vm2.x, vm2.y);
            ull E11 = f2pack(v11.x, v11.y);
            ull E22 = f2pack(v22.x, v22.y);
            ull E12 = f2pack(v12.x, v12.y);
            #pragma unroll
            for (int o = 0; o < 13; o++) {
                int k = j - o;
                if (k >= 0 && k < 11) {
                    ull G = f2pack(CG[k], CG[k]);   // compile-time broadcast
                    a0[o] = f2fma(G, M1,  a0[o]);
                    a1[o] = f2fma(G, M2,  a1[o]);
                    a2[o] = f2fma(G, E11, a2[o]);
                    a3[o] = f2fma(G, E22, a3[o]);
                    a4[o] = f2fma(G, E12, a4[o]);
                }
            }
        }
        #pragma unroll
        for (int o = 0; o < 13; o++) {
            float2 MU1 = f2unpack(a0[o]);
            float2 MU2 = f2unpack(a1[o]);
            float2 E11 = f2unpack(a2[o]);
            float2 E22 = f2unpack(a3[o]);
            float2 E12 = f2unpack(a4[o]);
            #pragma unroll
            for (int l = 0; l < 2; l++) {
                float mu1 = l ? MU1.y : MU1.x;
                float mu2 = l ? MU2.y : MU2.x;
                float e11 = l ? E11.y : E11.x;
                float e22 = l ? E22.y : E22.x;
                float e12 = l ? E12.y : E12.x;
                float m11 = mu1 * mu1, m22 = mu2 * mu2, m12 = mu1 * mu2;
                float s11 = e11 - m11;
                float s22 = e22 - m22;
                float s12 = e12 - m12;
                float v1 = 2.f * s12 + C2;
                float v2 = s11 + s22 + C2;
                float num = (2.f * m12 + C1) * v1;
                float den = (m11 + m22 + C1) * v2;
                lsum += __fdividef(num, den);
            }
        }
    }
    __shared__ float sred[256];
    sred[threadIdx.x] = lsum;
    __syncthreads();
    #pragma unroll
    for (int off = 128; off; off >>= 1) {
        if (threadIdx.x < off) sred[threadIdx.x] += sred[threadIdx.x + off];
        __syncthreads();
    }
    if (threadIdx.x == 0) d_bsum[blockIdx.x] = sred[0];
}

// Deterministic final reduction over 1812 block sums.
__global__ void final_kernel(float* __restrict__ out) {
    __shared__ double sd[256];
    double s = 0.0;
    for (int i = threadIdx.x; i < 1812; i += 256) s += (double)d_bsum[i];
    sd[threadIdx.x] = s;
    __syncthreads();
    #pragma unroll
    for (int off = 128; off; off >>= 1) {
        if (threadIdx.x < off) sd[threadIdx.x] += sd[threadIdx.x + off];
        __syncthreads();
    }
    if (threadIdx.x == 0)
        out[0] = (float)(sd[0] / 12057136.0);   // 2 * 182^3
}

// ---------------------------------------------------------------------------

extern "C" void kernel_launch(void* const* d_in, const int* in_sizes, int n_in,
                              void* d_out, int out_size) {
    const float* img1 = (const float*)d_in[0];
    const float* img2 = (const float*)d_in[1];
    float* out = (float*)d_out;

    init_kernel<<<1, 1>>>();
    pass1_kernel<<<9216, 192>>>(img1, img2);   // 2*192*192 rows / 8
    pass2_kernel<<<4778, 256>>>();             // 5*2*192*7*91 threads
    pass3_kernel<<<1812, 256>>>();             // 2*182*14*91 threads (strip fast)
    final_kernel<<<1, 256>>>(out);
}

// round 15
// speedup vs baseline: 1.0974x; 1.0160x over previous
#include <cuda_runtime.h>
#include <cuda_fp16.h>

// ---------------------------------------------------------------------------
// SSIM 3D, 11-tap separable Gaussian, VALID. Round 15:
// R14 (best: 176.6us) + pass2 software pipelining: all 36 window loads
// issued up-front into a register buffer (MLP 36/warp), then FMA triangle.
// ---------------------------------------------------------------------------

typedef unsigned long long ull;

__device__ constexpr float CG[11] = {
    0.0010283817f, 0.0075987700f, 0.0360007700f, 0.1093607000f,
    0.2130055500f, 0.2660117200f,
    0.2130055500f, 0.1093607000f, 0.0360007700f, 0.0075987700f,
    0.0010283817f
};

__device__ __forceinline__ ull f2pack(float lo, float hi) {
    ull r; asm("mov.b64 %0, {%1, %2};" : "=l"(r) : "f"(lo), "f"(hi)); return r;
}
__device__ __forceinline__ float2 f2unpack(ull v) {
    float2 r; asm("mov.b64 {%0, %1}, %2;" : "=f"(r.x), "=f"(r.y) : "l"(v)); return r;
}
__device__ __forceinline__ ull f2fma(ull a, ull b, ull c) {
    ull d; asm("fma.rn.f32x2 %0, %1, %2, %3;" : "=l"(d) : "l"(a), "l"(b), "l"(c)); return d;
}

// s1: [f][n][d][h(192)][w(184 pad, 182 valid)]   half
// s2: [f][n][d][oh(182)][w(184 pad, 182 valid)]  half
static const size_t FS1 = (size_t)2 * 192 * 192 * 184;   // 13,565,952 halves
static const size_t FS2 = (size_t)2 * 192 * 182 * 184;   // 12,859,392 halves
__device__ __half d_s1[5 * FS1];
__device__ __half d_s2[5 * FS2];

__device__ unsigned d_minbits;
__device__ unsigned d_maxbits;
__device__ float    d_bsum[1812];

// ---------------------------------------------------------------------------

__global__ void init_kernel() {
    d_minbits = 0xFFFFFFFFu;
    d_maxbits = 0u;
}

__device__ __forceinline__ float mono2f(unsigned u) {
    return (u & 0x80000000u) ? __uint_as_float(u ^ 0x80000000u)
                             : __uint_as_float(~u);
}
__device__ __forceinline__ void mono_acc(float f, unsigned& mn, unsigned& mx) {
    unsigned u = __float_as_uint(f);
    u = (u & 0x80000000u) ? ~u : (u | 0x80000000u);
    mn = min(mn, u);
    mx = max(mx, u);
}

// ---------------------------------------------------------------------------
// Pass 1: W conv + 5 products + img1 min/max. Block = (n,d, 8 h-rows).
// 192 threads; float4 smem fill; half2 stores. (Byte-identical to R7/R14.)
// ---------------------------------------------------------------------------
__global__ void __launch_bounds__(192) pass1_kernel(
    const float* __restrict__ img1, const float* __restrict__ img2) {
    __shared__ float sx[8 * 192];
    __shared__ float sy[8 * 192];

    int hg = blockIdx.x % 24;
    int nd = blockIdx.x / 24;          // n*192 + d
    int h0 = hg * 8;
    size_t base = ((size_t)nd * 192 + h0) * 192;
    int tid = threadIdx.x;

    unsigned lmin = 0xFFFFFFFFu, lmax = 0u;
    const float4* p1 = (const float4*)(img1 + base);
    const float4* p2 = (const float4*)(img2 + base);
    #pragma unroll
    for (int j = 0; j < 2; j++) {
        int idx = tid + j * 192;       // 0..383 float4
        float4 a = __ldg(&p1[idx]);
        float4 b = __ldg(&p2[idx]);
        ((float4*)sx)[idx] = a;
        ((float4*)sy)[idx] = b;
        mono_acc(a.x, lmin, lmax); mono_acc(a.y, lmin, lmax);
        mono_acc(a.z, lmin, lmax); mono_acc(a.w, lmin, lmax);
    }
    __syncthreads();

    size_t ob = ((size_t)nd * 192 + h0) * 184;
    for (int i = tid; i < 8 * 91; i += 192) {
        int r = i / 91;
        int p = (i % 91) * 2;          // ow pair: p, p+1
        float a0l = 0.f, a1l = 0.f, a2l = 0.f, a3l = 0.f, a4l = 0.f;
        float a0h = 0.f, a1h = 0.f, a2h = 0.f, a3h = 0.f, a4h = 0.f;
        #pragma unroll
        for (int k = 0; k < 11; k++) {
            float g = CG[k];
            float x = sx[r * 192 + p + k];
            float y = sy[r * 192 + p + k];
            float tx = g * x, ty = g * y;
            a0l += tx; a1l += ty; a2l += tx * x; a3l += ty * y; a4l += tx * y;
            float x2 = sx[r * 192 + p + 1 + k];
            float y2 = sy[r * 192 + p + 1 + k];
            float tx2 = g * x2, ty2 = g * y2;
            a0h += tx2; a1h += ty2; a2h += tx2 * x2; a3h += ty2 * y2; a4h += tx2 * y2;
        }
        size_t o = ob + (size_t)r * 184 + p;
        *(__half2*)&d_s1[o]           = __floats2half2_rn(a0l, a0h);
        *(__half2*)&d_s1[FS1 + o]     = __floats2half2_rn(a1l, a1h);
        *(__half2*)&d_s1[2 * FS1 + o] = __floats2half2_rn(a2l, a2h);
        *(__half2*)&d_s1[3 * FS1 + o] = __floats2half2_rn(a3l, a3h);
        *(__half2*)&d_s1[4 * FS1 + o] = __floats2half2_rn(a4l, a4h);
    }

    // min/max block reduce -> atomics
    #pragma unroll
    for (int off = 16; off; off >>= 1) {
        lmin = min(lmin, __shfl_down_sync(0xFFFFFFFFu, lmin, off));
        lmax = max(lmax, __shfl_down_sync(0xFFFFFFFFu, lmax, off));
    }
    __shared__ unsigned smin[6], smax[6];
    int wid = tid >> 5, lane = tid & 31;
    if (lane == 0) { smin[wid] = lmin; smax[wid] = lmax; }
    __syncthreads();
    if (tid == 0) {
        #pragma unroll
        for (int i = 1; i < 6; i++) {
            lmin = min(lmin, smin[i]);
            lmax = max(lmax, smax[i]);
        }
        atomicMin(&d_minbits, lmin);
        atomicMax(&d_maxbits, lmax);
    }
}

// ---------------------------------------------------------------------------
// Pass 2: H conv, strips of 26. ALL 36 window half2 loads issued up-front
// (register buffer, MLP 36/warp), then fp32 FMA triangle, then 26 stores.
// __launch_bounds__(256,2) gives ptxas 128 regs to keep the buffer live.
// ---------------------------------------------------------------------------
__global__ void __launch_bounds__(256, 2) pass2_kernel() {
    const size_t TOT = (size_t)5 * 2 * 192 * 7 * 91;     // 1,223,040
    size_t idx = (size_t)blockIdx.x * 256 + threadIdx.x;
    if (idx >= TOT) return;
    int owp = (int)(idx % 91); size_t t = idx / 91;
    int strip = (int)(t % 7); t /= 7;
    int f   = (int)(t % 5);
    int nd  = 383 - (int)(t / 5);        // descending: hit pass1's L2 tail
    int h0 = strip * 26;
    int ow = owp * 2;

    const __half* __restrict__ src = d_s1 + (size_t)f * FS1 + (size_t)nd * (192 * 184) + ow;
    __half* __restrict__ dst = d_s2 + (size_t)f * FS2 + (size_t)nd * (182 * 184) + ow;

    // load entire 36-row window up-front: independent LDGs, imm offsets
    __half2 v[36];
    #pragma unroll
    for (int j = 0; j < 36; j++)
        v[j] = __ldg((const __half2*)&src[(size_t)(h0 + j) * 184]);

    float accl[26], acch[26];
    #pragma unroll
    for (int o = 0; o < 26; o++) { accl[o] = 0.f; acch[o] = 0.f; }

    #pragma unroll
    for (int j = 0; j < 36; j++) {
        float vl = __low2float(v[j]), vh = __high2float(v[j]);
        #pragma unroll
        for (int o = 0; o < 26; o++) {
            int k = j - o;
            if (k >= 0 && k < 11) {
                accl[o] += CG[k] * vl;
                acch[o] += CG[k] * vh;
            }
        }
    }
    #pragma unroll
    for (int o = 0; o < 26; o++)
        *(__half2*)&dst[(size_t)(h0 + o) * 184] = __floats2half2_rn(accl[o], acch[o]);
}

// ---------------------------------------------------------------------------
// Pass 3: D conv (5 fields) + SSIM + block sum. Thread = (n, oh, strip, owp),
// strip varies FAST (halo L2 reuse). 2 adjacent ow per thread; f32x2
// accumulators (fp32-exact). C1/C2 derived inline. (Identical to R14.)
// ---------------------------------------------------------------------------
__global__ void __launch_bounds__(256) pass3_kernel() {
    const size_t TOT = (size_t)2 * 182 * 14 * 91;   // 463,736
    size_t idx = (size_t)blockIdx.x * 256 + threadIdx.x;
    float lsum = 0.f;
    if (idx < TOT) {
        int owp = (int)(idx % 91); size_t t = idx / 91;
        int strip = (int)(t % 14); t /= 14;          // strip fast: halo L2 reuse
        int oh = (int)(t % 182);
        int n  = (int)(t / 182);
        int d0 = strip * 13;

        float mxv = mono2f(d_maxbits);
        float mnv = mono2f(d_minbits);
        float max_val = (mxv > 128.0f) ? 255.0f : 1.0f;
        float min_val = (mnv < -0.5f) ? -1.0f : 0.0f;
        float Lr = max_val - min_val;
        float c1 = 0.01f * Lr, c2 = 0.03f * Lr;
        const float C1 = c1 * c1;
        const float C2 = c2 * c2;

        ull a0[13], a1[13], a2[13], a3[13], a4[13];
        #pragma unroll
        for (int o = 0; o < 13; o++) {
            a0[o] = 0; a1[o] = 0; a2[o] = 0; a3[o] = 0; a4[o] = 0;
        }
        // s2 offset: ((n*192 + d)*182 + oh)*184 + ow ; d-stride = 182*184 = 33488
        size_t pbase = ((size_t)(n * 192 + d0) * 182 + oh) * 184 + (size_t)(owp * 2);
        #pragma unroll
        for (int j = 0; j < 23; j++) {
            size_t p = pbase + (size_t)j * 33488;
            float2 vm1 = __half22float2(__ldg((const __half2*)&d_s2[p]));
            float2 vm2 = __half22float2(__ldg((const __half2*)&d_s2[p + FS2]));
            float2 v11 = __half22float2(__ldg((const __half2*)&d_s2[p + 2 * FS2]));
            float2 v22 = __half22float2(__ldg((const __half2*)&d_s2[p + 3 * FS2]));
            float2 v12 = __half22float2(__ldg((const __half2*)&d_s2[p + 4 * FS2]));
            ull M1  = f2pack(vm1.x, vm1.y);
            ull M2  = f2pack(vm2.x, vm2.y);
            ull E11 = f2pack(v11.x, v11.y);
            ull E22 = f2pack(v22.x, v22.y);
            ull E12 = f2pack(v12.x, v12.y);
            #pragma unroll
            for (int o = 0; o < 13; o++) {
                int k = j - o;
                if (k >= 0 && k < 11) {
                    ull G = f2pack(CG[k], CG[k]);   // compile-time broadcast
                    a0[o] = f2fma(G, M1,  a0[o]);
                    a1[o] = f2fma(G, M2,  a1[o]);
                    a2[o] = f2fma(G, E11, a2[o]);
                    a3[o] = f2fma(G, E22, a3[o]);
                    a4[o] = f2fma(G, E12, a4[o]);
                }
            }
        }
        #pragma unroll
        for (int o = 0; o < 13; o++) {
            float2 MU1 = f2unpack(a0[o]);
            float2 MU2 = f2unpack(a1[o]);
            float2 E11 = f2unpack(a2[o]);
            float2 E22 = f2unpack(a3[o]);
            float2 E12 = f2unpack(a4[o]);
            #pragma unroll
            for (int l = 0; l < 2; l++) {
                float mu1 = l ? MU1.y : MU1.x;
                float mu2 = l ? MU2.y : MU2.x;
                float e11 = l ? E11.y : E11.x;
                float e22 = l ? E22.y : E22.x;
                float e12 = l ? E12.y : E12.x;
                float m11 = mu1 * mu1, m22 = mu2 * mu2, m12 = mu1 * mu2;
                float s11 = e11 - m11;
                float s22 = e22 - m22;
                float s12 = e12 - m12;
                float v1 = 2.f * s12 + C2;
                float v2 = s11 + s22 + C2;
                float num = (2.f * m12 + C1) * v1;
                float den = (m11 + m22 + C1) * v2;
                lsum += __fdividef(num, den);
            }
        }
    }
    __shared__ float sred[256];
    sred[threadIdx.x] = lsum;
    __syncthreads();
    #pragma unroll
    for (int off = 128; off; off >>= 1) {
        if (threadIdx.x < off) sred[threadIdx.x] += sred[threadIdx.x + off];
        __syncthreads();
    }
    if (threadIdx.x == 0) d_bsum[blockIdx.x] = sred[0];
}

// Deterministic final reduction over 1812 block sums.
__global__ void final_kernel(float* __restrict__ out) {
    __shared__ double sd[256];
    double s = 0.0;
    for (int i = threadIdx.x; i < 1812; i += 256) s += (double)d_bsum[i];
    sd[threadIdx.x] = s;
    __syncthreads();
    #pragma unroll
    for (int off = 128; off; off >>= 1) {
        if (threadIdx.x < off) sd[threadIdx.x] += sd[threadIdx.x + off];
        __syncthreads();
    }
    if (threadIdx.x == 0)
        out[0] = (float)(sd[0] / 12057136.0);   // 2 * 182^3
}

// ---------------------------------------------------------------------------

extern "C" void kernel_launch(void* const* d_in, const int* in_sizes, int n_in,
                              void* d_out, int out_size) {
    const float* img1 = (const float*)d_in[0];
    const float* img2 = (const float*)d_in[1];
    float* out = (float*)d_out;

    init_kernel<<<1, 1>>>();
    pass1_kernel<<<9216, 192>>>(img1, img2);   // 2*192*192 rows / 8
    pass2_kernel<<<4778, 256>>>();             // 5*2*192*7*91 threads
    pass3_kernel<<<1812, 256>>>();             // 2*182*14*91 threads (strip fast)
    final_kernel<<<1, 256>>>(out);
}